// round 3
// baseline (speedup 1.0000x reference)
#include <cuda_runtime.h>

// ---------------------------------------------------------------------------
// BaoCypherNet on GB300 — fused gather-GEMM tree-conv network, fp32 f32x2 path
//
// Shapes: B=2048, C_IN=128, N=128, M=127
//   L1: [256,384]x[384,127] per tree, L2: [128,768]x[768,127], L3: [64,384]x[384,127]
// LayerNorm is a per-tree scalar (mean, 1/(std+1e-5)) over the raw conv output
// (incl. the zero column); applied lazily at the NEXT layer's gather together
// with leaky-relu. Final: maxpool over nodes -> 64->32 leaky -> 32->1.
// ---------------------------------------------------------------------------

#define B_TREES 2048
#define M_CONV  127

// Scratch (device globals: sanctioned scratch mechanism; no allocations).
__device__ float g_Y1[(size_t)2048 * 256 * 128];   // raw conv1 output, col0 never written (=0)
__device__ float g_Y2[(size_t)2048 * 128 * 128];   // raw conv2 output
__device__ float g_Y3[(size_t)2048 * 64  * 128];   // raw conv3 output
__device__ float g_s1[3][2048];                    // per-layer, per-tree sum
__device__ float g_s2[3][2048];                    // per-layer, per-tree sum of squares

__global__ void zero_stats_kernel() {
    int i = blockIdx.x * blockDim.x + threadIdx.x;
    if (i < 3 * 2048) {
        (&g_s1[0][0])[i] = 0.f;
        (&g_s2[0][0])[i] = 0.f;
    }
}

// ---- packed f32x2 helpers (sm_103a FFMA2 path: 2x fp32 throughput) ----------
__device__ __forceinline__ unsigned long long pack_dup(float a) {
    unsigned long long r;
    asm("mov.b64 %0, {%1, %1};" : "=l"(r) : "r"(__float_as_uint(a)));
    return r;
}
__device__ __forceinline__ void fma2(unsigned long long& acc,
                                     unsigned long long a, unsigned long long b) {
    asm("fma.rn.f32x2 %0, %1, %2, %0;" : "+l"(acc) : "l"(a), "l"(b));
}
__device__ __forceinline__ float2 unpack2(unsigned long long v) {
    unsigned lo, hi;
    asm("mov.b64 {%0, %1}, %2;" : "=r"(lo), "=r"(hi) : "l"(v));
    return make_float2(__uint_as_float(lo), __uint_as_float(hi));
}

// ---------------------------------------------------------------------------
// conv layer: out[b,o,m] = bias[o] + sum_{c,k} W[o,c,k] * Xn[b,c,idx[b,3m+k]]
// where Xn = input for LAYER==1 (raw trees), else leaky((Yprev-mu)/(std+eps)).
// Writes raw output to column m+1 of Y (col 0 stays 0 = zero-init, never
// written). Accumulates sum / sumsq of written values into g_s1/g_s2[LAYER-1].
// Tile: 64(o) x 64(m), K-chunks of 32, 256 threads, 4x4 microtile per thread.
// ---------------------------------------------------------------------------
template <int CIN, int COUT, int LAYER>
__global__ __launch_bounds__(256, 2) void conv_kernel(
    const float* __restrict__ trees,
    const int*   __restrict__ indexes,
    const float* __restrict__ W,
    const float* __restrict__ bias)
{
    constexpr int K  = 3 * CIN;
    constexpr int KB = 32;
    constexpr bool NORM = (LAYER > 1);

    const float* __restrict__ X = (LAYER == 1) ? trees : (LAYER == 2 ? g_Y1 : g_Y2);
    float* __restrict__ Y = (LAYER == 1) ? g_Y1 : (LAYER == 2 ? g_Y2 : g_Y3);

    __shared__ unsigned long long As[64][KB];      // weights, pre-duplicated {w,w}
    __shared__ __align__(16) float Bs[KB][64];     // gathered activations
    __shared__ int   sidx[3 * 64];
    __shared__ float snorm[2];
    __shared__ float sred[512];

    const int b  = blockIdx.z;
    const int m0 = blockIdx.x * 64;
    const int o0 = blockIdx.y * 64;
    const int tid = threadIdx.x;
    const int tx = tid & 15;        // m-group
    const int ty = tid >> 4;        // o-group

    if (NORM) {
        if (tid == 0) {
            constexpr float np = (LAYER == 2) ? (256.f * 128.f) : (128.f * 128.f);
            float s1 = g_s1[LAYER - 2][b];
            float s2 = g_s2[LAYER - 2][b];
            float mu = s1 / np;
            float var = fmaxf((s2 - s1 * mu) / (np - 1.f), 0.f);
            snorm[0] = mu;
            snorm[1] = 1.f / (sqrtf(var) + 1e-5f);
        }
    }
    if (tid < 192) {
        int m = m0 + tid / 3;
        sidx[tid] = (m < M_CONV) ? indexes[b * (3 * M_CONV) + m * 3 + (tid % 3)] : 0;
    }
    __syncthreads();

    float mean = 0.f, scale = 1.f;
    if (NORM) { mean = snorm[0]; scale = snorm[1]; }

    unsigned long long acc[4][2];
#pragma unroll
    for (int i = 0; i < 4; i++) { acc[i][0] = 0ull; acc[i][1] = 0ull; }

    const float* __restrict__ Xb = X + (size_t)b * CIN * 128;

    for (int k0 = 0; k0 < K; k0 += KB) {
        // --- stage A tile: 64 rows x 32 k, duplicated into u64 pairs ---
#pragma unroll
        for (int t = 0; t < 2; t++) {
            int f   = tid + t * 256;
            int row = f >> 3;
            int seg = (f & 7) * 4;
            float4 w4 = *reinterpret_cast<const float4*>(
                W + (size_t)(o0 + row) * K + k0 + seg);
            As[row][seg + 0] = pack_dup(w4.x);
            As[row][seg + 1] = pack_dup(w4.y);
            As[row][seg + 2] = pack_dup(w4.z);
            As[row][seg + 3] = pack_dup(w4.w);
        }
        // --- stage B tile: gather + (optional) LN + leaky ---
        {
            int bmm = tid & 63;
            int bk0 = tid >> 6;
#pragma unroll
            for (int t = 0; t < 8; t++) {
                int kk = bk0 + t * 4;
                int j  = k0 + kk;
                int c  = j / 3;
                int kr = j - 3 * c;
                int node = sidx[bmm * 3 + kr];
                float v;
                if (!NORM) {
                    v = Xb[c * 128 + node];          // trees col0 is stored 0
                } else {
                    float r = (node == 0) ? 0.f : Xb[c * 128 + node];
                    r = (r - mean) * scale;
                    v = (r > 0.f) ? r : 0.01f * r;
                }
                Bs[kk][bmm] = v;
            }
        }
        __syncthreads();

        // --- 4x4 microtile, packed fma2 over 32 k-steps ---
#pragma unroll
        for (int kk = 0; kk < KB; kk++) {
            ulonglong2 bv = *reinterpret_cast<const ulonglong2*>(&Bs[kk][tx * 4]);
#pragma unroll
            for (int i = 0; i < 4; i++) {
                unsigned long long av = As[ty * 4 + i][kk];
                fma2(acc[i][0], av, bv.x);
                fma2(acc[i][1], av, bv.y);
            }
        }
        __syncthreads();
    }

    // --- epilogue: bias, store to col m+1, partial LN stats ---
    float s1p = 0.f, s2p = 0.f;
#pragma unroll
    for (int i = 0; i < 4; i++) {
        int o = o0 + ty * 4 + i;
        float bv = bias[o];
        float2 p0 = unpack2(acc[i][0]);
        float2 p1 = unpack2(acc[i][1]);
        float vals[4] = {p0.x, p0.y, p1.x, p1.y};
#pragma unroll
        for (int jj = 0; jj < 4; jj++) {
            int m = m0 + tx * 4 + jj;
            if (m < M_CONV) {
                float val = vals[jj] + bv;
                Y[((size_t)b * COUT + o) * 128 + m + 1] = val;
                s1p += val;
                s2p += val * val;
            }
        }
    }
    sred[tid] = s1p;
    sred[256 + tid] = s2p;
    __syncthreads();
#pragma unroll
    for (int s = 128; s > 0; s >>= 1) {
        if (tid < s) {
            sred[tid]       += sred[tid + s];
            sred[256 + tid] += sred[256 + tid + s];
        }
        __syncthreads();
    }
    if (tid == 0) {
        atomicAdd(&g_s1[LAYER - 1][b], sred[0]);
        atomicAdd(&g_s2[LAYER - 1][b], sred[256]);
    }
}

// ---------------------------------------------------------------------------
// final: LN3 (no leaky) + maxpool over nodes + 64->32 leaky + 32->1
// scale > 0 so max over normalized == normalize(max over raw incl. col0=0).
// ---------------------------------------------------------------------------
__global__ __launch_bounds__(128) void final_kernel(
    const float* __restrict__ W4, const float* __restrict__ b4,
    const float* __restrict__ W5, const float* __restrict__ b5,
    float* __restrict__ out)
{
    const int b = blockIdx.x;
    const int tid = threadIdx.x;
    __shared__ float pooled[64];
    __shared__ float hbuf[32];

    const float np = 64.f * 128.f;
    float s1 = g_s1[2][b], s2 = g_s2[2][b];
    float mu = s1 / np;
    float var = fmaxf((s2 - s1 * mu) / (np - 1.f), 0.f);
    float scale = 1.f / (sqrtf(var) + 1e-5f);

    if (tid < 64) {
        const float* row = g_Y3 + ((size_t)b * 64 + tid) * 128;
        float mx = 0.f;                       // raw col0 value
        mx = fmaxf(mx, row[1]);
        mx = fmaxf(mx, row[2]);
        mx = fmaxf(mx, row[3]);
        const float4* r4 = reinterpret_cast<const float4*>(row);
#pragma unroll
        for (int i = 1; i < 32; i++) {
            float4 v = r4[i];
            mx = fmaxf(mx, fmaxf(fmaxf(v.x, v.y), fmaxf(v.z, v.w)));
        }
        pooled[tid] = (mx - mu) * scale;
    }
    __syncthreads();
    if (tid < 32) {
        float acc = b4[tid];
#pragma unroll
        for (int c = 0; c < 64; c++) acc += pooled[c] * W4[tid * 64 + c];
        hbuf[tid] = (acc > 0.f) ? acc : 0.01f * acc;
    }
    __syncthreads();
    if (tid < 32) {
        float p = hbuf[tid] * W5[tid];
#pragma unroll
        for (int off = 16; off; off >>= 1) p += __shfl_down_sync(0xffffffffu, p, off);
        if (tid == 0) out[b] = p + b5[0];
    }
}

// ---------------------------------------------------------------------------
extern "C" void kernel_launch(void* const* d_in, const int* in_sizes, int n_in,
                              void* d_out, int out_size)
{
    const float *trees, *W1, *b1, *W2, *b2, *W3, *b3, *W4, *b4, *W5, *b5;
    const int* indexes;

    if (in_sizes[1] == 3 * M_CONV * B_TREES) {
        // setup_inputs dict order: trees, indexes, W1,b1,W2,b2,W3,b3,W4,b4,W5,b5
        trees   = (const float*)d_in[0];
        indexes = (const int*)  d_in[1];
        W1 = (const float*)d_in[2];  b1 = (const float*)d_in[3];
        W2 = (const float*)d_in[4];  b2 = (const float*)d_in[5];
        W3 = (const float*)d_in[6];  b3 = (const float*)d_in[7];
        W4 = (const float*)d_in[8];  b4 = (const float*)d_in[9];
        W5 = (const float*)d_in[10]; b5 = (const float*)d_in[11];
    } else {
        // reference-arg order: trees, W1,b1,...,W5,b5, indexes
        trees = (const float*)d_in[0];
        W1 = (const float*)d_in[1];  b1 = (const float*)d_in[2];
        W2 = (const float*)d_in[3];  b2 = (const float*)d_in[4];
        W3 = (const float*)d_in[5];  b3 = (const float*)d_in[6];
        W4 = (const float*)d_in[7];  b4 = (const float*)d_in[8];
        W5 = (const float*)d_in[9];  b5 = (const float*)d_in[10];
        indexes = (const int*)d_in[11];
    }
    float* out = (float*)d_out;

    zero_stats_kernel<<<24, 256>>>();
    conv_kernel<128, 256, 1><<<dim3(2, 4, B_TREES), 256>>>(trees, indexes, W1, b1);
    conv_kernel<256, 128, 2><<<dim3(2, 2, B_TREES), 256>>>(trees, indexes, W2, b2);
    conv_kernel<128,  64, 3><<<dim3(2, 1, B_TREES), 256>>>(trees, indexes, W3, b3);
    final_kernel<<<B_TREES, 128>>>(W4, b4, W5, b5, out);
}

// round 8
// speedup vs baseline: 3.9091x; 3.9091x over previous
#include <cuda_runtime.h>
#include <cuda_bf16.h>
#include <cstdint>

// ===========================================================================
// BaoCypherNet on GB300 — tcgen05 bf16(hi/lo split) batched gather-GEMM.
// PERSISTENT CTAs: grid=148, one CTA per SM, TMEM alloc/dealloc ONCE per CTA,
// loop over trees. Arch-guarded SIMT fp32 fallback for the generic target.
// D[COUT,128] = W[COUT,K] x G^T[128,K]; lazy LayerNorm+leaky at next gather.
// Y[b][o][n]: n = conv position m (0..126), col 127 garbage (never gathered,
// excluded from stats; next layer reads col node-1, node>=1).
// MMA: SS cg1 kind::f16, M=128, N=64, K16 steps, SW128 K-major, desc+2/K16.
// ===========================================================================

#if defined(__CUDA_ARCH__) && (defined(__CUDA_ARCH_FEAT_SM103_ALL) || defined(__CUDA_ARCH_FEAT_SM100_ALL))
#define HAS_TCGEN05 1
#else
#define HAS_TCGEN05 0
#endif

#define B_TREES 2048
#define GRID_P  148

// ----------------------------- scratch -------------------------------------
__device__ float g_Y1[(size_t)2048 * 256 * 128];
__device__ float g_Y2[(size_t)2048 * 128 * 128];
__device__ float g_Y3[(size_t)2048 * 64 * 128];
__device__ float g_s1[3][2048];
__device__ float g_s2[3][2048];
// pre-split, pre-SW128-swizzled weight images; per (chunk, half128) 16KB block.
// All layers padded to M=128 rows per half (L3 rows 64..127 are zeros).
__device__ __nv_bfloat16 g_W1h[6 * 2 * 128 * 64], g_W1l[6 * 2 * 128 * 64];
__device__ __nv_bfloat16 g_W2h[12 * 128 * 64],    g_W2l[12 * 128 * 64];
__device__ __nv_bfloat16 g_W3h[6 * 128 * 64],     g_W3l[6 * 128 * 64];

__device__ __forceinline__ uint32_t swz(uint32_t byte_off) {
    return byte_off ^ ((byte_off >> 3) & 0x70);
}

#if HAS_TCGEN05
// ----------------------------- PTX helpers (sm_103a only) -------------------
__device__ __forceinline__ uint32_t smem_u32(const void* p) {
    uint32_t a;
    asm("{ .reg .u64 t; cvta.to.shared.u64 t, %1; cvt.u32.u64 %0, t; }"
        : "=r"(a) : "l"(p));
    return a;
}
__device__ __forceinline__ uint32_t elect_one() {
    uint32_t p;
    asm volatile("{ .reg .pred p; elect.sync _|p, 0xFFFFFFFF; selp.b32 %0,1,0,p; }"
                 : "=r"(p));
    return p;
}

#define TCGEN05_ALLOC(sm_addr, n) \
    asm volatile("tcgen05.alloc.cta_group::1.sync.aligned.shared::cta.b32 [%0], %1;" \
                 :: "r"((uint32_t)(sm_addr)), "r"((uint32_t)(n)) : "memory")
#define TCGEN05_DEALLOC(tm, n) \
    asm volatile("tcgen05.dealloc.cta_group::1.sync.aligned.b32 %0, %1;" :: "r"(tm), "r"((uint32_t)(n)))
#define TCGEN05_RELINQ() \
    asm volatile("tcgen05.relinquish_alloc_permit.cta_group::1.sync.aligned;")
#define TCGEN05_COMMIT(mbar) \
    asm volatile("tcgen05.commit.cta_group::1.mbarrier::arrive::one.shared::cluster.b64 [%0];" \
                 :: "r"((uint32_t)(mbar)) : "memory")
#define TCGEN05_WAIT_LD()  asm volatile("tcgen05.wait::ld.sync.aligned;" ::: "memory")
#define TCGEN05_FENCE_AFTER()  asm volatile("tcgen05.fence::after_thread_sync;" ::: "memory")
#define TCGEN05_FENCE_BEFORE() asm volatile("tcgen05.fence::before_thread_sync;" ::: "memory")
#define FENCE_ASYNC_SHARED() asm volatile("fence.proxy.async.shared::cta;" ::: "memory")
#define MBARRIER_INIT(mbar, cnt) \
    asm volatile("mbarrier.init.shared.b64 [%0], %1;" :: "r"((uint32_t)(mbar)), "r"((uint32_t)(cnt)) : "memory")
#define MBARRIER_INVAL(mbar) \
    asm volatile("mbarrier.inval.shared.b64 [%0];" :: "r"((uint32_t)(mbar)) : "memory")

#define MBARRIER_WAIT_PARITY(mbar_addr, parity) do {                               \
    uint32_t _m = (uint32_t)(mbar_addr);                                           \
    uint32_t _p = (uint32_t)(parity);                                              \
    uint32_t _done;                                                                \
    asm volatile("{\n\t.reg .pred p;\n\t"                                          \
        "mbarrier.try_wait.parity.acquire.cta.shared::cta.b64 p, [%1], %2;\n\t"    \
        "selp.b32 %0, 1, 0, p;\n\t}"                                               \
        : "=r"(_done) : "r"(_m), "r"(_p) : "memory");                              \
    if (!_done) {                                                                  \
        asm volatile("{\n\t.reg .pred P1;\n\t"                                     \
            "WL_%=:\n\t"                                                           \
            "mbarrier.try_wait.parity.acquire.cta.shared::cta.b64 P1, [%0], %1, 0x989680;\n\t" \
            "@P1 bra.uni WD_%=;\n\t"                                               \
            "bra.uni WL_%=;\n\t"                                                   \
            "WD_%=:\n\t}" :: "r"(_m), "r"(_p) : "memory");                         \
    }                                                                              \
} while (0)

#define TCGEN05_LD_X32(r, addr) \
    asm volatile("tcgen05.ld.sync.aligned.32x32b.x32.b32 " \
        "{%0, %1, %2, %3, %4, %5, %6, %7, %8, %9, %10, %11, %12, %13, %14, %15, " \
        " %16, %17, %18, %19, %20, %21, %22, %23, %24, %25, %26, %27, %28, %29, %30, %31}, [%32];" \
        : "=r"((r)[0]),  "=r"((r)[1]),  "=r"((r)[2]),  "=r"((r)[3]),  \
          "=r"((r)[4]),  "=r"((r)[5]),  "=r"((r)[6]),  "=r"((r)[7]),  \
          "=r"((r)[8]),  "=r"((r)[9]),  "=r"((r)[10]), "=r"((r)[11]), \
          "=r"((r)[12]), "=r"((r)[13]), "=r"((r)[14]), "=r"((r)[15]), \
          "=r"((r)[16]), "=r"((r)[17]), "=r"((r)[18]), "=r"((r)[19]), \
          "=r"((r)[20]), "=r"((r)[21]), "=r"((r)[22]), "=r"((r)[23]), \
          "=r"((r)[24]), "=r"((r)[25]), "=r"((r)[26]), "=r"((r)[27]), \
          "=r"((r)[28]), "=r"((r)[29]), "=r"((r)[30]), "=r"((r)[31]) \
        : "r"(addr))

#define STS128(addr, a0, a1, a2, a3) \
    asm volatile("st.shared.v4.b32 [%0], {%1, %2, %3, %4};" \
                 :: "r"(addr), "r"(a0), "r"(a1), "r"(a2), "r"(a3) : "memory")

// SW128 descriptor (LBO=1, SBO=64, version=1): rows of 128B, K-major.
__device__ __forceinline__ uint64_t mk_desc(uint32_t addr) {
    constexpr uint64_t BASE = (2ull << 61) | (1ull << 46) | (64ull << 32) | (1ull << 16);
    return BASE | ((uint64_t)(addr >> 4) & 0x3FFF);
}

// cg1 kind::f16 SS MMA (bf16 in, fp32 acc)
__device__ __forceinline__ void mma_f16_ss(uint32_t d, uint64_t a, uint64_t b,
                                           uint32_t idesc, bool acc) {
    uint32_t en = acc ? 1u : 0u;
    asm volatile("{\n\t.reg .pred p;\n\tsetp.ne.u32 p, %5, 0;\n\t"
        "tcgen05.mma.cta_group::1.kind::f16 [%0], %1, %2, %3, {%4, %4, %4, %4}, p;\n\t}"
        :: "r"(d), "l"(a), "l"(b), "r"(idesc), "r"(0u), "r"(en) : "memory");
}
#endif // HAS_TCGEN05

// --------------------------- weight prep -----------------------------------
__global__ void prep_w_kernel(const float* __restrict__ W1,
                              const float* __restrict__ W2,
                              const float* __restrict__ W3) {
    int bid = blockIdx.x;
    const float* W; __nv_bfloat16 *gh, *gl; int COUT, K, chunk, HALVES;
    if (bid < 6)       { W = W1; gh = g_W1h; gl = g_W1l; COUT = 256; K = 384; chunk = bid;      HALVES = 2; }
    else if (bid < 18) { W = W2; gh = g_W2h; gl = g_W2l; COUT = 128; K = 768; chunk = bid - 6;  HALVES = 1; }
    else               { W = W3; gh = g_W3h; gl = g_W3l; COUT = 64;  K = 384; chunk = bid - 18; HALVES = 1; }
    const int ROWS = HALVES * 128;
    char* bh = (char*)gh + (size_t)chunk * HALVES * 16384;
    char* bl = (char*)gl + (size_t)chunk * HALVES * 16384;
    for (int i = threadIdx.x; i < ROWS * 64; i += blockDim.x) {
        int o = i >> 6, k = i & 63;
        float w = (o < COUT) ? W[(size_t)o * K + chunk * 64 + k] : 0.f;
        __nv_bfloat16 h = __float2bfloat16(w);
        __nv_bfloat16 l = __float2bfloat16(w - __bfloat162float(h));
        uint32_t off = (uint32_t)(o >> 7) * 16384u + swz((uint32_t)((o & 127) * 128 + k * 2));
        *(__nv_bfloat16*)(bh + off) = h;
        *(__nv_bfloat16*)(bl + off) = l;
    }
}

// ------------------------------ conv layer (persistent) ---------------------
template <int CIN, int COUT, int LAYER>
__global__ __launch_bounds__(256, 1) void conv_tc(
    const float* __restrict__ trees,
    const int*   __restrict__ indexes,
    const float* __restrict__ Wraw,          // used only by SIMT fallback
    const float* __restrict__ bias)
{
    constexpr int K = 3 * CIN;
    constexpr int NCHUNK = K / 64;
    constexpr int HALVES = (COUT + 127) / 128;
    constexpr int A_BYTES = HALVES * 16384;
    constexpr int MAIN = 2 * A_BYTES + 32768;
    constexpr int TBYTES = 128 * 129 * 4;
    constexpr int REGION = (MAIN > TBYTES) ? MAIN : TBYTES;
    constexpr int OFF_AH = 0, OFF_AL = A_BYTES;
    constexpr int OFF_BH = 2 * A_BYTES, OFF_BL = 2 * A_BYTES + 16384;
    constexpr int OFF_IDX = REGION;
    constexpr int OFF_MISC = OFF_IDX + 1536;
    constexpr int OFF_RED = OFF_MISC + 32;

    extern __shared__ __align__(1024) char smem[];
    int*   sidx  = (int*)(smem + OFF_IDX);
    float* snorm = (float*)(smem + OFF_MISC + 16);
    float* sred  = (float*)(smem + OFF_RED);

    const int tid = threadIdx.x, wid = tid >> 5, lid = tid & 31;

    const float* __restrict__ Xall =
        (LAYER == 1) ? trees : (LAYER == 2) ? g_Y1 : g_Y2;
    float* __restrict__ Y = (LAYER == 1) ? g_Y1 : (LAYER == 2) ? g_Y2 : g_Y3;

#if HAS_TCGEN05
    // ===================== tcgen05 tensor-core path =========================
    // M=128, N=64 per MMA (validated geometry); two N-halves cover 128 cols.
    constexpr uint32_t IDESC = (1u << 4) | (1u << 7) | (1u << 10)
                             | (8u << 17) | (8u << 24);
    constexpr int NCOLS = HALVES * 128;

    const uint32_t sb = smem_u32(smem);
    const uint32_t mbar = sb + OFF_MISC + 8;

    // ---- one-time TMEM alloc + mbarrier init (per CTA lifetime) ----
    if (wid == 0) { TCGEN05_ALLOC(sb + OFF_MISC, NCOLS); }
    if (tid == 0) MBARRIER_INIT(mbar, 1);
    __syncthreads();
    const uint32_t tmem = *(volatile uint32_t*)(smem + OFF_MISC);

    const char* gWh = (LAYER == 1) ? (const char*)g_W1h :
                      (LAYER == 2) ? (const char*)g_W2h : (const char*)g_W3h;
    const char* gWl = (LAYER == 1) ? (const char*)g_W1l :
                      (LAYER == 2) ? (const char*)g_W2l : (const char*)g_W3l;

    int ph = 0;                            // running mbarrier phase

    for (int b = blockIdx.x; b < B_TREES; b += GRID_P) {
        const float* __restrict__ Xb = Xall + (size_t)b * CIN * 128;

        for (int i = tid; i < 384; i += 256)
            sidx[i] = (i < 381) ? indexes[b * 381 + i] : 0;
        if (LAYER > 1 && tid == 0) {
            constexpr float np = (LAYER == 2) ? (256.f * 128.f) : (128.f * 128.f);
            float s1 = g_s1[LAYER - 2][b], s2 = g_s2[LAYER - 2][b];
            float mmu = s1 / np;
            float var = fmaxf((s2 - s1 * mmu) / (np - 1.f), 0.f);
            snorm[0] = mmu;
            snorm[1] = 1.f / (sqrtf(var) + 1e-5f);
        }
        __syncthreads();
        float mu = 0.f, scale = 1.f;
        if (LAYER > 1) { mu = snorm[0]; scale = snorm[1]; }

        for (int c0 = 0; c0 < NCHUNK; c0++) {
            // ---- A: straight copy of pre-swizzled W chunk (hi + lo) ----
            {
                const uint4* sh = (const uint4*)(gWh + (size_t)c0 * A_BYTES);
                const uint4* sl = (const uint4*)(gWl + (size_t)c0 * A_BYTES);
                uint4* dh = (uint4*)(smem + OFF_AH);
                uint4* dl = (uint4*)(smem + OFF_AL);
                for (int i = tid; i < A_BYTES / 16; i += 256) { dh[i] = sh[i]; dl[i] = sl[i]; }
            }
            // ---- B: gather + LN/leaky + hi/lo split, swizzled STS ----
            #pragma unroll
            for (int it = 0; it < 4; it++) {
                int seg = tid + it * 256;
                int n = seg >> 3, sg = seg & 7;
                float v[8];
                #pragma unroll
                for (int e = 0; e < 8; e++) {
                    int j = c0 * 64 + sg * 8 + e;
                    int ch = j / 3, kr = j - 3 * ch;
                    int node = sidx[n * 3 + kr];
                    float r;
                    if (LAYER == 1) {
                        r = Xb[ch * 128 + node];             // trees col0 == 0
                    } else {
                        r = node ? Xb[ch * 128 + node - 1] : 0.f;
                        r = (r - mu) * scale;
                        r = (r > 0.f) ? r : 0.01f * r;
                    }
                    v[e] = r;
                }
                uint32_t hp[4], lp[4];
                #pragma unroll
                for (int e = 0; e < 4; e++) {
                    __nv_bfloat16 h0 = __float2bfloat16(v[2 * e]);
                    __nv_bfloat16 h1 = __float2bfloat16(v[2 * e + 1]);
                    __nv_bfloat16 l0 = __float2bfloat16(v[2 * e] - __bfloat162float(h0));
                    __nv_bfloat16 l1 = __float2bfloat16(v[2 * e + 1] - __bfloat162float(h1));
                    hp[e] = (uint32_t)__bfloat16_as_ushort(h0) | ((uint32_t)__bfloat16_as_ushort(h1) << 16);
                    lp[e] = (uint32_t)__bfloat16_as_ushort(l0) | ((uint32_t)__bfloat16_as_ushort(l1) << 16);
                }
                uint32_t off = swz((uint32_t)(n * 128 + sg * 16));
                STS128(sb + OFF_BH + off, hp[0], hp[1], hp[2], hp[3]);
                STS128(sb + OFF_BL + off, lp[0], lp[1], lp[2], lp[3]);
            }
            FENCE_ASYNC_SHARED();
            __syncthreads();

            // ---- issue MMAs for this chunk (M=128, N=64 each) ----
            if (wid == 0 && elect_one()) {
                TCGEN05_FENCE_AFTER();
                #pragma unroll
                for (int h = 0; h < HALVES; h++) {
                    uint64_t adh = mk_desc(sb + OFF_AH + h * 16384);
                    uint64_t adl = mk_desc(sb + OFF_AL + h * 16384);
                    #pragma unroll
                    for (int nh = 0; nh < 2; nh++) {
                        uint32_t d = tmem + h * 128 + nh * 64;
                        uint64_t bdh = mk_desc(sb + OFF_BH + nh * 8192);
                        uint64_t bdl = mk_desc(sb + OFF_BL + nh * 8192);
                        #pragma unroll
                        for (int s = 0; s < 3; s++) {        // hh, lh, hl
                            uint64_t ad = (s == 1) ? adl : adh;
                            uint64_t bd = (s == 2) ? bdl : bdh;
                            #pragma unroll
                            for (int km = 0; km < 4; km++) {
                                bool acc = !(c0 == 0 && s == 0 && km == 0);
                                mma_f16_ss(d, ad + km * 2, bd + km * 2, IDESC, acc);
                            }
                        }
                    }
                }
                TCGEN05_COMMIT(mbar);
            }
            // ---- all threads wait before buffer reuse ----
            MBARRIER_WAIT_PARITY(mbar, ph & 1);
            ph++;
            TCGEN05_FENCE_AFTER();
        }

        // ---- epilogue: bias + stats + smem transpose + coalesced store ----
        float s1 = 0.f, s2 = 0.f;
        float* T = (float*)smem;                              // reuse A/B region
        __syncthreads();
        for (int h = 0; h < HALVES; h++) {
            if (wid < 4) {
                int row = wid * 32 + lid;
                int o = h * 128 + row;
                float bv = (o < COUT) ? bias[o] : 0.f;
                bool live = (o < COUT);
                #pragma unroll
                for (int nb = 0; nb < 4; nb++) {
                    uint32_t r[32];
                    TCGEN05_LD_X32(r, tmem + h * 128 + nb * 32);
                    TCGEN05_WAIT_LD();
                    #pragma unroll
                    for (int q = 0; q < 32; q++) {
                        int n = nb * 32 + q;
                        float val = __uint_as_float(r[q]) + bv;
                        T[row * 129 + n] = val;
                        if (live && n != 127) { s1 += val; s2 += val * val; }
                    }
                }
                TCGEN05_FENCE_BEFORE();
            }
            __syncthreads();
            for (int i = tid; i < 128 * 32; i += 256) {
                int o = i >> 5, q = i & 31;
                int oo = h * 128 + o;
                if (oo < COUT) {
                    const float* tr = T + o * 129 + q * 4;
                    float4 vv = make_float4(tr[0], tr[1], tr[2], tr[3]);
                    *(float4*)(Y + ((size_t)b * COUT + oo) * 128 + q * 4) = vv;
                }
            }
            __syncthreads();
        }

        sred[tid] = s1; sred[256 + tid] = s2;
        __syncthreads();
        #pragma unroll
        for (int s = 128; s > 0; s >>= 1) {
            if (tid < s) { sred[tid] += sred[tid + s]; sred[256 + tid] += sred[256 + tid + s]; }
            __syncthreads();
        }
        if (tid == 0) {
            g_s1[LAYER - 1][b] = sred[0];
            g_s2[LAYER - 1][b] = sred[256];
        }
        __syncthreads();
    }

    // ---- one-time teardown ----
    if (tid == 0) MBARRIER_INVAL(mbar);
    __syncthreads();
    if (wid == 0) { TCGEN05_RELINQ(); TCGEN05_DEALLOC(tmem, NCOLS); }

#else
    // ===================== SIMT fp32 fallback (generic target) ==============
    float* Ws  = (float*)smem;                  // 64 x 32
    float* Bsf = (float*)(smem + 8192);         // 32 x 68 (padded)
    const int tx = tid & 15, ty = tid >> 4;

    for (int b = blockIdx.x; b < B_TREES; b += GRID_P) {
        const float* __restrict__ Xb = Xall + (size_t)b * CIN * 128;
        __syncthreads();
        for (int i = tid; i < 384; i += 256)
            sidx[i] = (i < 381) ? indexes[b * 381 + i] : 0;
        if (LAYER > 1 && tid == 0) {
            constexpr float np = (LAYER == 2) ? (256.f * 128.f) : (128.f * 128.f);
            float s1 = g_s1[LAYER - 2][b], s2 = g_s2[LAYER - 2][b];
            float mmu = s1 / np;
            float var = fmaxf((s2 - s1 * mmu) / (np - 1.f), 0.f);
            snorm[0] = mmu;
            snorm[1] = 1.f / (sqrtf(var) + 1e-5f);
        }
        __syncthreads();
        float mu = 0.f, scale = 1.f;
        if (LAYER > 1) { mu = snorm[0]; scale = snorm[1]; }
        float s1 = 0.f, s2 = 0.f;

        for (int ot = 0; ot < COUT / 64; ot++) {
            for (int mt = 0; mt < 2; mt++) {
                float acc[4][4];
                #pragma unroll
                for (int i = 0; i < 4; i++)
                    #pragma unroll
                    for (int j = 0; j < 4; j++) acc[i][j] = 0.f;
                int o0 = ot * 64, m0 = mt * 64;
                for (int k0 = 0; k0 < K; k0 += 32) {
                    __syncthreads();
                    for (int i = tid; i < 2048; i += 256) {
                        int r = i >> 5, kk = i & 31;
                        Ws[r * 32 + kk] = Wraw[(size_t)(o0 + r) * K + k0 + kk];
                    }
                    for (int i = tid; i < 2048; i += 256) {
                        int kk = i >> 6, n = i & 63;
                        int j = k0 + kk;
                        int ch = j / 3, kr = j - 3 * ch;
                        int node = sidx[(m0 + n) * 3 + kr];
                        float r;
                        if (LAYER == 1) {
                            r = Xb[ch * 128 + node];
                        } else {
                            r = node ? Xb[ch * 128 + node - 1] : 0.f;
                            r = (r - mu) * scale;
                            r = (r > 0.f) ? r : 0.01f * r;
                        }
                        Bsf[kk * 68 + n] = r;
                    }
                    __syncthreads();
                    #pragma unroll
                    for (int kk = 0; kk < 32; kk++) {
                        float bvv[4];
                        #pragma unroll
                        for (int j = 0; j < 4; j++) bvv[j] = Bsf[kk * 68 + tx * 4 + j];
                        #pragma unroll
                        for (int i = 0; i < 4; i++) {
                            float av = Ws[(ty * 4 + i) * 32 + kk];
                            #pragma unroll
                            for (int j = 0; j < 4; j++) acc[i][j] += av * bvv[j];
                        }
                    }
                }
                __syncthreads();
                #pragma unroll
                for (int i = 0; i < 4; i++) {
                    int o = o0 + ty * 4 + i;
                    float bv = bias[o];
                    #pragma unroll
                    for (int j = 0; j < 4; j++) {
                        int m = m0 + tx * 4 + j;
                        if (m < 127) {
                            float val = acc[i][j] + bv;
                            Y[((size_t)b * COUT + o) * 128 + m] = val;
                            s1 += val; s2 += val * val;
                        }
                    }
                }
            }
        }
        sred[tid] = s1; sred[256 + tid] = s2;
        __syncthreads();
        #pragma unroll
        for (int s = 128; s > 0; s >>= 1) {
            if (tid < s) { sred[tid] += sred[tid + s]; sred[256 + tid] += sred[256 + tid + s]; }
            __syncthreads();
        }
        if (tid == 0) {
            g_s1[LAYER - 1][b] = sred[0];
            g_s2[LAYER - 1][b] = sred[256];
        }
    }
#endif
}

// ------------------------------ final MLP -----------------------------------
__global__ __launch_bounds__(128) void final_kernel(
    const float* __restrict__ W4, const float* __restrict__ b4,
    const float* __restrict__ W5, const float* __restrict__ b5,
    float* __restrict__ out)
{
    const int b = blockIdx.x;
    const int tid = threadIdx.x;
    __shared__ float pooled[64];
    __shared__ float hbuf[32];

    const float np = 64.f * 128.f;
    float s1 = g_s1[2][b], s2 = g_s2[2][b];
    float mu = s1 / np;
    float var = fmaxf((s2 - s1 * mu) / (np - 1.f), 0.f);
    float scale = 1.f / (sqrtf(var) + 1e-5f);

    if (tid < 64) {
        const float* row = g_Y3 + ((size_t)b * 64 + tid) * 128;
        float mx = 0.f;                                  // implicit zero column
        const float4* r4 = reinterpret_cast<const float4*>(row);
#pragma unroll
        for (int i = 0; i < 31; i++) {                   // cols 0..123
            float4 v = r4[i];
            mx = fmaxf(mx, fmaxf(fmaxf(v.x, v.y), fmaxf(v.z, v.w)));
        }
        mx = fmaxf(mx, row[124]);
        mx = fmaxf(mx, row[125]);
        mx = fmaxf(mx, row[126]);                        // 127 = garbage, excluded
        pooled[tid] = (mx - mu) * scale;
    }
    __syncthreads();
    if (tid < 32) {
        float acc = b4[tid];
#pragma unroll
        for (int c = 0; c < 64; c++) acc += pooled[c] * W4[tid * 64 + c];
        hbuf[tid] = (acc > 0.f) ? acc : 0.01f * acc;
    }
    __syncthreads();
    if (tid < 32) {
        float p = hbuf[tid] * W5[tid];
#pragma unroll
        for (int off = 16; off; off >>= 1) p += __shfl_down_sync(0xffffffffu, p, off);
        if (tid == 0) out[b] = p + b5[0];
    }
}

// ---------------------------------------------------------------------------
extern "C" void kernel_launch(void* const* d_in, const int* in_sizes, int n_in,
                              void* d_out, int out_size)
{
    const float *trees, *W1, *b1, *W2, *b2, *W3, *b3, *W4, *b4, *W5, *b5;
    const int* indexes;

    if (in_sizes[1] == 3 * 127 * B_TREES) {
        trees   = (const float*)d_in[0];
        indexes = (const int*)  d_in[1];
        W1 = (const float*)d_in[2];  b1 = (const float*)d_in[3];
        W2 = (const float*)d_in[4];  b2 = (const float*)d_in[5];
        W3 = (const float*)d_in[6];  b3 = (const float*)d_in[7];
        W4 = (const float*)d_in[8];  b4 = (const float*)d_in[9];
        W5 = (const float*)d_in[10]; b5 = (const float*)d_in[11];
    } else {
        trees = (const float*)d_in[0];
        W1 = (const float*)d_in[1];  b1 = (const float*)d_in[2];
        W2 = (const float*)d_in[3];  b2 = (const float*)d_in[4];
        W3 = (const float*)d_in[5];  b3 = (const float*)d_in[6];
        W4 = (const float*)d_in[7];  b4 = (const float*)d_in[8];
        W5 = (const float*)d_in[9];  b5 = (const float*)d_in[10];
        indexes = (const int*)d_in[11];
    }
    float* out = (float*)d_out;

    // smem: L1 region 98304, L2/L3 region 66048; + idx/misc/red 3616
    const int SMEM1 = 98304 + 1536 + 32 + 2048;   // 101920
    const int SMEM2 = 66048 + 1536 + 32 + 2048;   // 69664
    cudaFuncSetAttribute(conv_tc<128, 256, 1>, cudaFuncAttributeMaxDynamicSharedMemorySize, SMEM1);
    cudaFuncSetAttribute(conv_tc<256, 128, 2>, cudaFuncAttributeMaxDynamicSharedMemorySize, SMEM2);
    cudaFuncSetAttribute(conv_tc<128, 64, 3>,  cudaFuncAttributeMaxDynamicSharedMemorySize, SMEM2);

    prep_w_kernel<<<24, 256>>>(W1, W2, W3);
    conv_tc<128, 256, 1><<<GRID_P, 256, SMEM1>>>(trees, indexes, W1, b1);
    conv_tc<256, 128, 2><<<GRID_P, 256, SMEM2>>>(trees, indexes, W2, b2);
    conv_tc<128, 64, 3><<<GRID_P, 256, SMEM2>>>(trees, indexes, W3, b3);
    final_kernel<<<B_TREES, 128>>>(W4, b4, W5, b5, out);
}

// round 9
// speedup vs baseline: 4.7519x; 1.2156x over previous
#include <cuda_runtime.h>
#include <cuda_bf16.h>
#include <cstdint>

// ===========================================================================
// BaoCypherNet on GB300 — tcgen05 bf16(hi/lo) gather-GEMM, persistent CTAs,
// double-buffered MMA pipeline, LN+activation+split fused into epilogues.
// Inter-layer data = packed u32 {hi bf16 | lo bf16<<16}, layout [b][c][128]
// where col 0 = normalized zero-node value and col n (n>=1) = position n-1.
// Gather is then a uniform u32 load at [c][node] for every layer.
// Layer-3 epilogue fuses maxpool + 64->32->1 MLP (scale>0 => max commutes).
// ===========================================================================

#if defined(__CUDA_ARCH__) && (defined(__CUDA_ARCH_FEAT_SM103_ALL) || defined(__CUDA_ARCH_FEAT_SM100_ALL))
#define HAS_TCGEN05 1
#else
#define HAS_TCGEN05 0
#endif

#define B_TREES 2048
#define GRID_P  148

// ----------------------------- scratch -------------------------------------
__device__ uint32_t g_X0[(size_t)2048 * 128 * 128];   // packed trees
__device__ uint32_t g_X1[(size_t)2048 * 256 * 128];   // packed LN(leaky(conv1))
__device__ uint32_t g_X2[(size_t)2048 * 128 * 128];   // packed LN(leaky(conv2))
__device__ float    g_raw[(size_t)2048 * 256 * 128];  // fallback-only scratch
// pre-split, pre-SW128-swizzled weight images; per (chunk, half128) 16KB block.
__device__ __nv_bfloat16 g_W1h[6 * 2 * 128 * 64], g_W1l[6 * 2 * 128 * 64];
__device__ __nv_bfloat16 g_W2h[12 * 128 * 64],    g_W2l[12 * 128 * 64];
__device__ __nv_bfloat16 g_W3h[6 * 128 * 64],     g_W3l[6 * 128 * 64];

__device__ __forceinline__ uint32_t swz(uint32_t byte_off) {
    return byte_off ^ ((byte_off >> 3) & 0x70);
}
__device__ __forceinline__ uint32_t pack_hl(float x) {
    __nv_bfloat16 h = __float2bfloat16(x);
    __nv_bfloat16 l = __float2bfloat16(x - __bfloat162float(h));
    return (uint32_t)__bfloat16_as_ushort(h) | ((uint32_t)__bfloat16_as_ushort(l) << 16);
}
__device__ __forceinline__ float unpack_hl(uint32_t p) {
    __nv_bfloat16 h = __ushort_as_bfloat16((unsigned short)(p & 0xFFFF));
    __nv_bfloat16 l = __ushort_as_bfloat16((unsigned short)(p >> 16));
    return __bfloat162float(h) + __bfloat162float(l);
}
__device__ __forceinline__ float leaky(float a) { return a > 0.f ? a : 0.01f * a; }

#if HAS_TCGEN05
// ----------------------------- PTX helpers (sm_103a only) -------------------
__device__ __forceinline__ uint32_t smem_u32(const void* p) {
    uint32_t a;
    asm("{ .reg .u64 t; cvta.to.shared.u64 t, %1; cvt.u32.u64 %0, t; }"
        : "=r"(a) : "l"(p));
    return a;
}
__device__ __forceinline__ uint32_t elect_one() {
    uint32_t p;
    asm volatile("{ .reg .pred p; elect.sync _|p, 0xFFFFFFFF; selp.b32 %0,1,0,p; }"
                 : "=r"(p));
    return p;
}

#define TCGEN05_ALLOC(sm_addr, n) \
    asm volatile("tcgen05.alloc.cta_group::1.sync.aligned.shared::cta.b32 [%0], %1;" \
                 :: "r"((uint32_t)(sm_addr)), "r"((uint32_t)(n)) : "memory")
#define TCGEN05_DEALLOC(tm, n) \
    asm volatile("tcgen05.dealloc.cta_group::1.sync.aligned.b32 %0, %1;" :: "r"(tm), "r"((uint32_t)(n)))
#define TCGEN05_RELINQ() \
    asm volatile("tcgen05.relinquish_alloc_permit.cta_group::1.sync.aligned;")
#define TCGEN05_COMMIT(mbar) \
    asm volatile("tcgen05.commit.cta_group::1.mbarrier::arrive::one.shared::cluster.b64 [%0];" \
                 :: "r"((uint32_t)(mbar)) : "memory")
#define TCGEN05_WAIT_LD()  asm volatile("tcgen05.wait::ld.sync.aligned;" ::: "memory")
#define TCGEN05_FENCE_AFTER()  asm volatile("tcgen05.fence::after_thread_sync;" ::: "memory")
#define TCGEN05_FENCE_BEFORE() asm volatile("tcgen05.fence::before_thread_sync;" ::: "memory")
#define FENCE_ASYNC_SHARED() asm volatile("fence.proxy.async.shared::cta;" ::: "memory")
#define MBARRIER_INIT(mbar, cnt) \
    asm volatile("mbarrier.init.shared.b64 [%0], %1;" :: "r"((uint32_t)(mbar)), "r"((uint32_t)(cnt)) : "memory")
#define MBARRIER_INVAL(mbar) \
    asm volatile("mbarrier.inval.shared.b64 [%0];" :: "r"((uint32_t)(mbar)) : "memory")

#define MBARRIER_WAIT_PARITY(mbar_addr, parity) do {                               \
    uint32_t _m = (uint32_t)(mbar_addr);                                           \
    uint32_t _p = (uint32_t)(parity);                                              \
    uint32_t _done;                                                                \
    asm volatile("{\n\t.reg .pred p;\n\t"                                          \
        "mbarrier.try_wait.parity.acquire.cta.shared::cta.b64 p, [%1], %2;\n\t"    \
        "selp.b32 %0, 1, 0, p;\n\t}"                                               \
        : "=r"(_done) : "r"(_m), "r"(_p) : "memory");                              \
    if (!_done) {                                                                  \
        asm volatile("{\n\t.reg .pred P1;\n\t"                                     \
            "WL_%=:\n\t"                                                           \
            "mbarrier.try_wait.parity.acquire.cta.shared::cta.b64 P1, [%0], %1, 0x989680;\n\t" \
            "@P1 bra.uni WD_%=;\n\t"                                               \
            "bra.uni WL_%=;\n\t"                                                   \
            "WD_%=:\n\t}" :: "r"(_m), "r"(_p) : "memory");                         \
    }                                                                              \
} while (0)

#define TCGEN05_LD_X32(r, addr) \
    asm volatile("tcgen05.ld.sync.aligned.32x32b.x32.b32 " \
        "{%0, %1, %2, %3, %4, %5, %6, %7, %8, %9, %10, %11, %12, %13, %14, %15, " \
        " %16, %17, %18, %19, %20, %21, %22, %23, %24, %25, %26, %27, %28, %29, %30, %31}, [%32];" \
        : "=r"((r)[0]),  "=r"((r)[1]),  "=r"((r)[2]),  "=r"((r)[3]),  \
          "=r"((r)[4]),  "=r"((r)[5]),  "=r"((r)[6]),  "=r"((r)[7]),  \
          "=r"((r)[8]),  "=r"((r)[9]),  "=r"((r)[10]), "=r"((r)[11]), \
          "=r"((r)[12]), "=r"((r)[13]), "=r"((r)[14]), "=r"((r)[15]), \
          "=r"((r)[16]), "=r"((r)[17]), "=r"((r)[18]), "=r"((r)[19]), \
          "=r"((r)[20]), "=r"((r)[21]), "=r"((r)[22]), "=r"((r)[23]), \
          "=r"((r)[24]), "=r"((r)[25]), "=r"((r)[26]), "=r"((r)[27]), \
          "=r"((r)[28]), "=r"((r)[29]), "=r"((r)[30]), "=r"((r)[31]) \
        : "r"(addr))

#define STS128(addr, a0, a1, a2, a3) \
    asm volatile("st.shared.v4.b32 [%0], {%1, %2, %3, %4};" \
                 :: "r"(addr), "r"(a0), "r"(a1), "r"(a2), "r"(a3) : "memory")

// SW128 descriptor (LBO=1, SBO=64, version=1): rows of 128B, K-major.
__device__ __forceinline__ uint64_t mk_desc(uint32_t addr) {
    constexpr uint64_t BASE = (2ull << 61) | (1ull << 46) | (64ull << 32) | (1ull << 16);
    return BASE | ((uint64_t)(addr >> 4) & 0x3FFF);
}

// cg1 kind::f16 SS MMA (bf16 in, fp32 acc)
__device__ __forceinline__ void mma_f16_ss(uint32_t d, uint64_t a, uint64_t b,
                                           uint32_t idesc, bool acc) {
    uint32_t en = acc ? 1u : 0u;
    asm volatile("{\n\t.reg .pred p;\n\tsetp.ne.u32 p, %5, 0;\n\t"
        "tcgen05.mma.cta_group::1.kind::f16 [%0], %1, %2, %3, {%4, %4, %4, %4}, p;\n\t}"
        :: "r"(d), "l"(a), "l"(b), "r"(idesc), "r"(0u), "r"(en) : "memory");
}
#endif // HAS_TCGEN05

// --------------------------- prep kernels -----------------------------------
__global__ void prep_w_kernel(const float* __restrict__ W1,
                              const float* __restrict__ W2,
                              const float* __restrict__ W3) {
    int bid = blockIdx.x;
    const float* W; __nv_bfloat16 *gh, *gl; int COUT, K, chunk, HALVES;
    if (bid < 6)       { W = W1; gh = g_W1h; gl = g_W1l; COUT = 256; K = 384; chunk = bid;      HALVES = 2; }
    else if (bid < 18) { W = W2; gh = g_W2h; gl = g_W2l; COUT = 128; K = 768; chunk = bid - 6;  HALVES = 1; }
    else               { W = W3; gh = g_W3h; gl = g_W3l; COUT = 64;  K = 384; chunk = bid - 18; HALVES = 1; }
    const int ROWS = HALVES * 128;
    char* bh = (char*)gh + (size_t)chunk * HALVES * 16384;
    char* bl = (char*)gl + (size_t)chunk * HALVES * 16384;
    for (int i = threadIdx.x; i < ROWS * 64; i += blockDim.x) {
        int o = i >> 6, k = i & 63;
        float w = (o < COUT) ? W[(size_t)o * K + chunk * 64 + k] : 0.f;
        __nv_bfloat16 h = __float2bfloat16(w);
        __nv_bfloat16 l = __float2bfloat16(w - __bfloat162float(h));
        uint32_t off = (uint32_t)(o >> 7) * 16384u + swz((uint32_t)((o & 127) * 128 + k * 2));
        *(__nv_bfloat16*)(bh + off) = h;
        *(__nv_bfloat16*)(bl + off) = l;
    }
}

__global__ void prep_x_kernel(const float* __restrict__ trees) {
    size_t base = (size_t)blockIdx.x * 16384;
    for (int i = threadIdx.x; i < 16384; i += 256)
        g_X0[base + i] = pack_hl(trees[base + i]);
}

// ------------------------------ conv layer (persistent) ---------------------
template <int CIN, int COUT, int LAYER>
__global__ __launch_bounds__(256, 1) void conv_tc(
    const int*   __restrict__ indexes,
    const float* __restrict__ Wraw,          // fallback only
    const float* __restrict__ bias,
    const float* __restrict__ W4, const float* __restrict__ b4,
    const float* __restrict__ W5, const float* __restrict__ b5,
    float* __restrict__ out)
{
    constexpr int K = 3 * CIN;
    constexpr int NCHUNK = K / 64;
    constexpr int HALVES = (COUT + 127) / 128;
    constexpr int A_BYTES = HALVES * 16384;           // one precision
    constexpr int AB_STAGE = 2 * A_BYTES + 32768;     // Ah+Al+Bh+Bl per stage
    constexpr int TBYTES = COUT * 129 * 4;
    constexpr int REGION = (2 * AB_STAGE > TBYTES) ? 2 * AB_STAGE : TBYTES;
    constexpr int OFF_IDX = REGION;
    constexpr int OFF_MBAR = OFF_IDX + 1536;
    constexpr int OFF_RED = OFF_MBAR + 48;

    extern __shared__ __align__(1024) char smem[];
    int*   sidx  = (int*)(smem + OFF_IDX);
    float* snorm = (float*)(smem + OFF_MBAR + 16);
    float* sred  = (float*)(smem + OFF_RED);

    const int tid = threadIdx.x, wid = tid >> 5, lid = tid & 31;

    const uint32_t* __restrict__ Xin =
        (LAYER == 1) ? g_X0 : (LAYER == 2) ? g_X1 : g_X2;
    uint32_t* __restrict__ Xout = (LAYER == 1) ? g_X1 : g_X2;

#if HAS_TCGEN05
    // ===================== tcgen05 tensor-core path =========================
    constexpr uint32_t IDESC = (1u << 4) | (1u << 7) | (1u << 10)
                             | (8u << 17) | (8u << 24);   // f32acc bf16 N=64 M=128
    constexpr int NCOLS = HALVES * 128;

    const uint32_t sb = smem_u32(smem);

    if (wid == 0) { TCGEN05_ALLOC(sb + OFF_MBAR + 32, NCOLS); }   // tmem ptr slot
    if (tid == 0) { MBARRIER_INIT(sb + OFF_MBAR, 1); MBARRIER_INIT(sb + OFF_MBAR + 8, 1); }
    __syncthreads();
    const uint32_t tmem = *(volatile uint32_t*)(smem + OFF_MBAR + 32);

    const char* gWh = (LAYER == 1) ? (const char*)g_W1h :
                      (LAYER == 2) ? (const char*)g_W2h : (const char*)g_W3h;
    const char* gWl = (LAYER == 1) ? (const char*)g_W1l :
                      (LAYER == 2) ? (const char*)g_W2l : (const char*)g_W3l;

    int use[2] = {0, 0};

    for (int b = blockIdx.x; b < B_TREES; b += GRID_P) {
        const uint32_t* __restrict__ Xb = Xin + (size_t)b * CIN * 128;

        for (int i = tid; i < 384; i += 256)
            sidx[i] = (i < 381) ? indexes[b * 381 + i] : 0;
        __syncthreads();

        for (int c0 = 0; c0 < NCHUNK; c0++) {
            const int s = c0 & 1;
            const int SA = s * AB_STAGE;
            const int OFF_AH = SA, OFF_AL = SA + A_BYTES;
            const int OFF_BH = SA + 2 * A_BYTES, OFF_BL = SA + 2 * A_BYTES + 16384;

            if (use[s] > 0)
                MBARRIER_WAIT_PARITY(sb + OFF_MBAR + s * 8, (use[s] - 1) & 1);

            // ---- A: straight copy of pre-swizzled W chunk (hi + lo) ----
            {
                const uint4* sh = (const uint4*)(gWh + (size_t)c0 * A_BYTES);
                const uint4* sl = (const uint4*)(gWl + (size_t)c0 * A_BYTES);
                uint4* dh = (uint4*)(smem + OFF_AH);
                uint4* dl = (uint4*)(smem + OFF_AL);
                for (int i = tid; i < A_BYTES / 16; i += 256) { dh[i] = sh[i]; dl[i] = sl[i]; }
            }
            // ---- B: pure packed gather (no float math) ----
            #pragma unroll
            for (int it = 0; it < 4; it++) {
                int seg = tid + it * 256;
                int n = seg >> 3, sg = seg & 7;
                uint32_t v[8];
                #pragma unroll
                for (int e = 0; e < 8; e++) {
                    int j = c0 * 64 + sg * 8 + e;
                    int ch = j / 3, kr = j - 3 * ch;
                    v[e] = Xb[ch * 128 + sidx[n * 3 + kr]];
                }
                uint32_t hp[4], lp[4];
                #pragma unroll
                for (int e = 0; e < 4; e++) {
                    hp[e] = __byte_perm(v[2 * e], v[2 * e + 1], 0x5410);
                    lp[e] = __byte_perm(v[2 * e], v[2 * e + 1], 0x7632);
                }
                uint32_t off = swz((uint32_t)(n * 128 + sg * 16));
                STS128(sb + OFF_BH + off, hp[0], hp[1], hp[2], hp[3]);
                STS128(sb + OFF_BL + off, lp[0], lp[1], lp[2], lp[3]);
            }
            FENCE_ASYNC_SHARED();
            __syncthreads();

            // ---- issue MMAs for this chunk (M=128, N=64 each) ----
            if (wid == 0 && elect_one()) {
                TCGEN05_FENCE_AFTER();
                #pragma unroll
                for (int h = 0; h < HALVES; h++) {
                    uint64_t adh = mk_desc(sb + OFF_AH + h * 16384);
                    uint64_t adl = mk_desc(sb + OFF_AL + h * 16384);
                    #pragma unroll
                    for (int nh = 0; nh < 2; nh++) {
                        uint32_t d = tmem + h * 128 + nh * 64;
                        uint64_t bdh = mk_desc(sb + OFF_BH + nh * 8192);
                        uint64_t bdl = mk_desc(sb + OFF_BL + nh * 8192);
                        #pragma unroll
                        for (int q = 0; q < 3; q++) {        // hh, lh, hl
                            uint64_t ad = (q == 1) ? adl : adh;
                            uint64_t bd = (q == 2) ? bdl : bdh;
                            #pragma unroll
                            for (int km = 0; km < 4; km++) {
                                bool acc = !(c0 == 0 && q == 0 && km == 0);
                                mma_f16_ss(d, ad + km * 2, bd + km * 2, IDESC, acc);
                            }
                        }
                    }
                }
                TCGEN05_COMMIT(sb + OFF_MBAR + s * 8);
            }
            use[s]++;
            // NO wait here — next chunk stages the other buffer (pipeline).
        }

        // ---- drain both buffers, then epilogue ----
        #pragma unroll
        for (int s = 0; s < 2; s++)
            if (use[s] > 0)
                MBARRIER_WAIT_PARITY(sb + OFF_MBAR + s * 8, (use[s] - 1) & 1);
        TCGEN05_FENCE_AFTER();

        // pass 1: LDTM once, stash raw+bias into T (col0 = 0), stats
        float* T = (float*)smem;
        float s1 = 0.f, s2 = 0.f;
        constexpr int NWARP = (LAYER == 3) ? 2 : 4;
        if (wid < NWARP) {
            #pragma unroll
            for (int h = 0; h < HALVES; h++) {
                int row = wid * 32 + lid;
                int o = h * 128 + row;
                if (o < COUT) {
                    float bv = bias[o];
                    float* Tr = T + o * 129;
                    Tr[0] = 0.f;
                    #pragma unroll
                    for (int nb = 0; nb < 4; nb++) {
                        uint32_t r[32];
                        TCGEN05_LD_X32(r, tmem + h * 128 + nb * 32);
                        TCGEN05_WAIT_LD();
                        #pragma unroll
                        for (int q = 0; q < 32; q++) {
                            int n = nb * 32 + q;
                            if (n < 127) {
                                float val = __uint_as_float(r[q]) + bv;
                                Tr[n + 1] = val;
                                s1 += val; s2 += val * val;
                            }
                        }
                    }
                }
            }
            TCGEN05_FENCE_BEFORE();
        }
        sred[tid] = s1; sred[256 + tid] = s2;
        __syncthreads();
        #pragma unroll
        for (int st = 128; st > 0; st >>= 1) {
            if (tid < st) { sred[tid] += sred[tid + st]; sred[256 + tid] += sred[256 + tid + st]; }
            __syncthreads();
        }
        if (tid == 0) {
            constexpr float np = (float)(COUT * 128);
            float t1 = sred[0], t2 = sred[256];
            float mmu = t1 / np;
            float var = fmaxf((t2 - t1 * mmu) / (np - 1.f), 0.f);
            snorm[0] = mmu;
            snorm[1] = 1.f / (sqrtf(var) + 1e-5f);
        }
        __syncthreads();
        const float mu = snorm[0], scale = snorm[1];

        if (LAYER < 3) {
            // pass 2: normalize + leaky + pack + coalesced store
            for (int i = tid; i < COUT * 32; i += 256) {
                int o = i >> 5, q = i & 31;
                const float* tr = T + o * 129 + q * 4;
                uint4 pv;
                pv.x = pack_hl(leaky((tr[0] - mu) * scale));
                pv.y = pack_hl(leaky((tr[1] - mu) * scale));
                pv.z = pack_hl(leaky((tr[2] - mu) * scale));
                pv.w = pack_hl(leaky((tr[3] - mu) * scale));
                *(uint4*)(Xout + ((size_t)b * COUT + o) * 128 + q * 4) = pv;
            }
        } else {
            // fused maxpool + MLP  (LN3 has no leaky; scale>0 => max commutes)
            float* pooled = sred;         // reuse (stats consumed)
            float* hbuf = sred + 96;
            if (tid < 64) {
                const float* Tr = T + tid * 129;
                float mx = Tr[0];
                #pragma unroll
                for (int c = 1; c < 128; c++) mx = fmaxf(mx, Tr[c]);
                pooled[tid] = (mx - mu) * scale;
            }
            __syncthreads();
            if (tid < 32) {
                float acc = b4[tid];
                #pragma unroll
                for (int c = 0; c < 64; c++) acc += pooled[c] * W4[tid * 64 + c];
                hbuf[tid] = leaky(acc);
            }
            __syncthreads();
            if (tid < 32) {
                float p = hbuf[tid] * W5[tid];
                #pragma unroll
                for (int off = 16; off; off >>= 1) p += __shfl_down_sync(0xffffffffu, p, off);
                if (tid == 0) out[b] = p + b5[0];
            }
        }
        __syncthreads();
    }

    // ---- one-time teardown ----
    if (tid == 0) { MBARRIER_INVAL(sb + OFF_MBAR); MBARRIER_INVAL(sb + OFF_MBAR + 8); }
    __syncthreads();
    if (wid == 0) { TCGEN05_RELINQ(); TCGEN05_DEALLOC(tmem, NCOLS); }

#else
    // ===================== SIMT fp32 fallback (generic target) ==============
    float* Ws  = (float*)smem;                  // 64 x 32
    float* Bsf = (float*)(smem + 8192);         // 32 x 68 (padded)
    const int tx = tid & 15, ty = tid >> 4;

    for (int b = blockIdx.x; b < B_TREES; b += GRID_P) {
        const uint32_t* __restrict__ Xb = Xin + (size_t)b * CIN * 128;
        __syncthreads();
        for (int i = tid; i < 384; i += 256)
            sidx[i] = (i < 381) ? indexes[b * 381 + i] : 0;
        __syncthreads();
        float s1 = 0.f, s2 = 0.f;

        for (int ot = 0; ot < COUT / 64; ot++) {
            for (int mt = 0; mt < 2; mt++) {
                float acc[4][4];
                #pragma unroll
                for (int i = 0; i < 4; i++)
                    #pragma unroll
                    for (int j = 0; j < 4; j++) acc[i][j] = 0.f;
                int o0 = ot * 64, m0 = mt * 64;
                for (int k0 = 0; k0 < K; k0 += 32) {
                    __syncthreads();
                    for (int i = tid; i < 2048; i += 256) {
                        int r = i >> 5, kk = i & 31;
                        Ws[r * 32 + kk] = Wraw[(size_t)(o0 + r) * K + k0 + kk];
                    }
                    for (int i = tid; i < 2048; i += 256) {
                        int kk = i >> 6, n = i & 63;
                        int j = k0 + kk;
                        int ch = j / 3, kr = j - 3 * ch;
                        Bsf[kk * 68 + n] = unpack_hl(Xb[ch * 128 + sidx[(m0 + n) * 3 + kr]]);
                    }
                    __syncthreads();
                    #pragma unroll
                    for (int kk = 0; kk < 32; kk++) {
                        float bvv[4];
                        #pragma unroll
                        for (int j = 0; j < 4; j++) bvv[j] = Bsf[kk * 68 + tx * 4 + j];
                        #pragma unroll
                        for (int i = 0; i < 4; i++) {
                            float av = Ws[(ty * 4 + i) * 32 + kk];
                            #pragma unroll
                            for (int j = 0; j < 4; j++) acc[i][j] += av * bvv[j];
                        }
                    }
                }
                __syncthreads();
                #pragma unroll
                for (int i = 0; i < 4; i++) {
                    int o = o0 + ty * 4 + i;
                    float bv = bias[o];
                    #pragma unroll
                    for (int j = 0; j < 4; j++) {
                        int m = m0 + tx * 4 + j;
                        if (m < 127) {
                            float val = acc[i][j] + bv;
                            g_raw[((size_t)b * COUT + o) * 128 + m] = val;
                            s1 += val; s2 += val * val;
                        }
                    }
                }
            }
        }
        sred[tid] = s1; sred[256 + tid] = s2;
        __syncthreads();
        #pragma unroll
        for (int st = 128; st > 0; st >>= 1) {
            if (tid < st) { sred[tid] += sred[tid + st]; sred[256 + tid] += sred[256 + tid + st]; }
            __syncthreads();
        }
        if (tid == 0) {
            float np = (float)(COUT * 128);
            float t1 = sred[0], t2 = sred[256];
            float mmu = t1 / np;
            float var = fmaxf((t2 - t1 * mmu) / (np - 1.f), 0.f);
            snorm[0] = mmu;
            snorm[1] = 1.f / (sqrtf(var) + 1e-5f);
        }
        __syncthreads();
        float mu = snorm[0], scale = snorm[1];

        if (LAYER < 3) {
            for (int i = tid; i < COUT * 128; i += 256) {
                int o = i >> 7, n = i & 127;
                float v = (n == 0) ? 0.f : g_raw[((size_t)b * COUT + o) * 128 + n - 1];
                Xout[((size_t)b * COUT + o) * 128 + n] = pack_hl(leaky((v - mu) * scale));
            }
        } else {
            float* pooled = sred;
            float* hbuf = sred + 96;
            if (tid < 64) {
                float mx = 0.f;
                for (int m = 0; m < 127; m++)
                    mx = fmaxf(mx, g_raw[((size_t)b * 64 + tid) * 128 + m]);
                pooled[tid] = (mx - mu) * scale;
            }
            __syncthreads();
            if (tid < 32) {
                float acc = b4[tid];
                #pragma unroll
                for (int c = 0; c < 64; c++) acc += pooled[c] * W4[tid * 64 + c];
                hbuf[tid] = leaky(acc);
            }
            __syncthreads();
            if (tid < 32) {
                float p = hbuf[tid] * W5[tid];
                #pragma unroll
                for (int off = 16; off; off >>= 1) p += __shfl_down_sync(0xffffffffu, p, off);
                if (tid == 0) out[b] = p + b5[0];
            }
        }
        __syncthreads();
    }
#endif
}

// ---------------------------------------------------------------------------
extern "C" void kernel_launch(void* const* d_in, const int* in_sizes, int n_in,
                              void* d_out, int out_size)
{
    const float *trees, *W1, *b1, *W2, *b2, *W3, *b3, *W4, *b4, *W5, *b5;
    const int* indexes;

    if (in_sizes[1] == 3 * 127 * B_TREES) {
        trees   = (const float*)d_in[0];
        indexes = (const int*)  d_in[1];
        W1 = (const float*)d_in[2];  b1 = (const float*)d_in[3];
        W2 = (const float*)d_in[4];  b2 = (const float*)d_in[5];
        W3 = (const float*)d_in[6];  b3 = (const float*)d_in[7];
        W4 = (const float*)d_in[8];  b4 = (const float*)d_in[9];
        W5 = (const float*)d_in[10]; b5 = (const float*)d_in[11];
    } else {
        trees = (const float*)d_in[0];
        W1 = (const float*)d_in[1];  b1 = (const float*)d_in[2];
        W2 = (const float*)d_in[3];  b2 = (const float*)d_in[4];
        W3 = (const float*)d_in[5];  b3 = (const float*)d_in[6];
        W4 = (const float*)d_in[7];  b4 = (const float*)d_in[8];
        W5 = (const float*)d_in[9];  b5 = (const float*)d_in[10];
        indexes = (const int*)d_in[11];
    }
    float* out = (float*)d_out;

    // smem: L1 region 196608 (2 stages of 96KB) / T 132096 -> 196608
    //       L2/L3 region 131072 / T 66048|33024 -> 131072 ; + idx/mbar/red
    const int SMEM1 = 196608 + 1536 + 48 + 2048;   // 200240
    const int SMEM2 = 131072 + 1536 + 48 + 2048;   // 134704
    cudaFuncSetAttribute(conv_tc<128, 256, 1>, cudaFuncAttributeMaxDynamicSharedMemorySize, SMEM1);
    cudaFuncSetAttribute(conv_tc<256, 128, 2>, cudaFuncAttributeMaxDynamicSharedMemorySize, SMEM2);
    cudaFuncSetAttribute(conv_tc<128, 64, 3>,  cudaFuncAttributeMaxDynamicSharedMemorySize, SMEM2);

    prep_w_kernel<<<24, 256>>>(W1, W2, W3);
    prep_x_kernel<<<B_TREES, 256>>>(trees);
    conv_tc<128, 256, 1><<<GRID_P, 256, SMEM1>>>(indexes, W1, b1, nullptr, nullptr, nullptr, nullptr, nullptr);
    conv_tc<256, 128, 2><<<GRID_P, 256, SMEM2>>>(indexes, W2, b2, nullptr, nullptr, nullptr, nullptr, nullptr);
    conv_tc<128, 64, 3><<<GRID_P, 256, SMEM2>>>(indexes, W3, b3, W4, b4, W5, b5, out);
}